// round 1
// baseline (speedup 1.0000x reference)
#include <cuda_runtime.h>
#include <cuda_bf16.h>

// Problem constants
#define BB 4
#define CC 64
#define TT 128
#define FF 128
#define HH 128
#define KK 8
#define LL 121          // F - K + 1
#define NN 512          // B*T
#define D0 512          // C*K
#define DH 256          // 2*H
#define MROWS 61952     // L*N
#define COLS4H 1024     // 2*4H

// Scratch buffers (static device allocations - allowed)
__device__ float g_xn[4194304];       // (B,C,T,F) normed input
__device__ float g_hA[31719424];      // (L*N, 512) h0 / ping-pong
__device__ float g_hB[15859712];      // (L*N, 256) ping-pong
__device__ float g_U[63438848];       // (L*N, 1024) GEMM output / P buffer

__device__ __forceinline__ float* buf_ptr(int id) {
    switch (id) {
        case 0: return g_hA;
        case 1: return g_hB;
        default: return g_U;
    }
}

// ---------------------------------------------------------------------------
// 1) Channel norm over C for each (b,t,f)
// ---------------------------------------------------------------------------
__global__ __launch_bounds__(256) void norm_kernel(
    const float* __restrict__ x, const float* __restrict__ gamma,
    const float* __restrict__ beta)
{
    int idx = blockIdx.x * 256 + threadIdx.x;   // over B*T*F = 65536
    int f = idx & 127;
    int t = (idx >> 7) & 127;
    int b = idx >> 14;
    long base = ((long)b * CC * TT * FF) + (long)t * FF + f;
    const float* xp = x + base;
    float v[CC];
    float s = 0.f;
#pragma unroll
    for (int c = 0; c < CC; ++c) { v[c] = xp[(long)c * TT * FF]; s += v[c]; }
    float mu = s * (1.f / 64.f);
    float vs = 0.f;
#pragma unroll
    for (int c = 0; c < CC; ++c) { float d = v[c] - mu; vs += d * d; }
    float inv = rsqrtf(vs * (1.f / 64.f) + 1e-8f);
    float* op = g_xn + base;
#pragma unroll
    for (int c = 0; c < CC; ++c)
        op[(long)c * TT * FF] = gamma[c] * (v[c] - mu) * inv + beta[c];
}

// ---------------------------------------------------------------------------
// 2) Unfold: h0[(l*N+n)*512 + c*8+k] = xn[b,c,t,l+k]
// ---------------------------------------------------------------------------
__global__ __launch_bounds__(256) void unfold_kernel()
{
    long o = (long)blockIdx.x * 256 + threadIdx.x;
    if (o >= 31719424L) return;
    int col = (int)(o & 511);
    int k = col & 7;
    int c = col >> 3;
    long row = o >> 9;          // l*512 + n
    int n = (int)(row & 511);
    int l = (int)(row >> 9);
    int b = n >> 7;
    int t = n & 127;
    g_hA[o] = g_xn[(((long)(b * CC + c) * TT + t) << 7) + l + k];
}

// ---------------------------------------------------------------------------
// 3) SGEMM: C(MxN) = A(MxK) * B(KxN), all row-major.
//    128x128 block tile, BK=8, 256 threads, 8x8 per-thread tile.
//    M % 128 == 0, N % 128 == 0, K % 8 == 0 guaranteed.
// ---------------------------------------------------------------------------
__global__ __launch_bounds__(256) void sgemm_kernel(
    int aId, const float* __restrict__ B, int cId, int M, int N, int K)
{
    const float* __restrict__ A = buf_ptr(aId);
    float* __restrict__ C = buf_ptr(cId);

    __shared__ float As[8][128];
    __shared__ float Bs[8][128];

    const int tid = threadIdx.x;
    const long bm = (long)blockIdx.y * 128;
    const long bn = (long)blockIdx.x * 128;

    const int tx = (tid & 15) * 8;
    const int ty = (tid >> 4) * 8;

    const int arow = tid >> 1;          // 0..127
    const int acol = (tid & 1) * 4;     // 0 or 4
    const int brow = tid >> 5;          // 0..7
    const int bcol = (tid & 31) * 4;    // 0..124

    const float* Aptr = A + (bm + arow) * (long)K + acol;
    const float* Bptr = B + (long)brow * N + bn + bcol;

    float acc[8][8];
#pragma unroll
    for (int i = 0; i < 8; ++i)
#pragma unroll
        for (int j = 0; j < 8; ++j) acc[i][j] = 0.f;

    for (int k0 = 0; k0 < K; k0 += 8) {
        float4 a = *(const float4*)(Aptr + k0);
        As[acol + 0][arow] = a.x;
        As[acol + 1][arow] = a.y;
        As[acol + 2][arow] = a.z;
        As[acol + 3][arow] = a.w;
        float4 b = *(const float4*)(Bptr + (long)k0 * N);
        *(float4*)&Bs[brow][bcol] = b;
        __syncthreads();
#pragma unroll
        for (int kk = 0; kk < 8; ++kk) {
            float4 a0 = *(const float4*)&As[kk][ty];
            float4 a1 = *(const float4*)&As[kk][ty + 4];
            float4 b0 = *(const float4*)&Bs[kk][tx];
            float4 b1 = *(const float4*)&Bs[kk][tx + 4];
            float ar[8] = {a0.x, a0.y, a0.z, a0.w, a1.x, a1.y, a1.z, a1.w};
            float br_[8] = {b0.x, b0.y, b0.z, b0.w, b1.x, b1.y, b1.z, b1.w};
#pragma unroll
            for (int i = 0; i < 8; ++i)
#pragma unroll
                for (int j = 0; j < 8; ++j)
                    acc[i][j] = fmaf(ar[i], br_[j], acc[i][j]);
        }
        __syncthreads();
    }

#pragma unroll
    for (int i = 0; i < 8; ++i) {
        float* Crow = C + (bm + ty + i) * (long)N + bn + tx;
        *(float4*)(Crow + 0) = make_float4(acc[i][0], acc[i][1], acc[i][2], acc[i][3]);
        *(float4*)(Crow + 4) = make_float4(acc[i][4], acc[i][5], acc[i][6], acc[i][7]);
    }
}

// ---------------------------------------------------------------------------
// 4) SRU scan: reads U (L*N, 1024) = [dir0: z f r hp | dir1: z f r hp],
//    applies sigmoid with biases, runs recurrence over L, writes (L*N, 256).
// ---------------------------------------------------------------------------
__global__ __launch_bounds__(256) void scan_kernel(
    int outId, const float* __restrict__ bf, const float* __restrict__ br)
{
    const float* __restrict__ U = g_U;
    float* __restrict__ hout = buf_ptr(outId);

    int t = blockIdx.x * 256 + threadIdx.x;   // 131072 threads
    int hidx = t & 127;
    int n = (t >> 7) & 511;
    int dir = t >> 16;

    float bfv = bf[dir * HH + hidx];
    float brv = br[dir * HH + hidx];

    long ubase = (long)n * COLS4H + dir * 512 + hidx;
    long obase = (long)n * DH + dir * HH + hidx;

    float c = 0.f;
    if (dir == 0) {
        for (int l = 0; l < LL; ++l) {
            const float* u = U + ubase + (long)l * NN * COLS4H;
            float z = u[0], fg = u[128], r = u[256], hp = u[384];
            fg = 1.f / (1.f + __expf(-(fg + bfv)));
            r = 1.f / (1.f + __expf(-(r + brv)));
            c = fg * c + (1.f - fg) * z;
            hout[obase + (long)l * NN * DH] = r * c + (1.f - r) * hp;
        }
    } else {
        for (int l = LL - 1; l >= 0; --l) {
            const float* u = U + ubase + (long)l * NN * COLS4H;
            float z = u[0], fg = u[128], r = u[256], hp = u[384];
            fg = 1.f / (1.f + __expf(-(fg + bfv)));
            r = 1.f / (1.f + __expf(-(r + brv)));
            c = fg * c + (1.f - fg) * z;
            hout[obase + (long)l * NN * DH] = r * c + (1.f - r) * hp;
        }
    }
}

// ---------------------------------------------------------------------------
// 5) ConvTranspose gather + bias + residual.
//    P (in g_U): (L*N, 512), P[l*N+n][c*8+k] = sum_h2 rnn[n,h2,l]*convW[h2,c,k]
//    out[n,c,f] = convb[c] + sum_k P[(f-k)*N+n][c*8+k] + xn[b,c,t,f]
// ---------------------------------------------------------------------------
__global__ __launch_bounds__(128) void gather_kernel(
    const float* __restrict__ convb, float* __restrict__ out)
{
    __shared__ float sP[LL * 9 + 8];
    int c = blockIdx.x;
    int n = blockIdx.y;
    int f = threadIdx.x;

    for (int idx = f; idx < LL * 8; idx += 128) {
        int l = idx >> 3, j = idx & 7;
        sP[l * 9 + j] = g_U[((long)(l * NN + n)) * 512 + c * 8 + j];
    }
    __syncthreads();

    float acc = convb[c];
#pragma unroll
    for (int k = 0; k < 8; ++k) {
        int l = f - k;
        if (l >= 0 && l < LL) acc += sP[l * 9 + k];
    }
    int b = n >> 7, t = n & 127;
    long oi = (((long)(b * CC + c) * TT + t) << 7) + f;
    out[oi] = acc + g_xn[oi];
}

// ---------------------------------------------------------------------------
// Launch
// ---------------------------------------------------------------------------
extern "C" void kernel_launch(void* const* d_in, const int* in_sizes, int n_in,
                              void* d_out, int out_size)
{
    const float* x     = (const float*)d_in[0];
    const float* gamma = (const float*)d_in[1];
    const float* beta  = (const float*)d_in[2];
    const float* W0  = (const float*)d_in[3];
    const float* bf0 = (const float*)d_in[4];
    const float* br0 = (const float*)d_in[5];
    const float* W1  = (const float*)d_in[6];
    const float* bf1 = (const float*)d_in[7];
    const float* br1 = (const float*)d_in[8];
    const float* W2  = (const float*)d_in[9];
    const float* bf2 = (const float*)d_in[10];
    const float* br2 = (const float*)d_in[11];
    const float* W3  = (const float*)d_in[12];
    const float* bf3 = (const float*)d_in[13];
    const float* br3 = (const float*)d_in[14];
    const float* convW = (const float*)d_in[15];
    const float* convb = (const float*)d_in[16];
    float* out = (float*)d_out;

    // 1) channel norm
    norm_kernel<<<256, 256>>>(x, gamma, beta);
    // 2) unfold -> g_hA (L*N, 512)
    unfold_kernel<<<123904, 256>>>();

    dim3 g8(8, 484), g4(4, 484);

    // Layer 0: A=g_hA(0) K=512 -> U, scan -> g_hB(1)
    sgemm_kernel<<<g8, 256>>>(0, W0, 2, MROWS, COLS4H, 512);
    scan_kernel<<<512, 256>>>(1, bf0, br0);
    // Layer 1: A=g_hB(1) K=256 -> U, scan -> g_hA(0)
    sgemm_kernel<<<g8, 256>>>(1, W1, 2, MROWS, COLS4H, 256);
    scan_kernel<<<512, 256>>>(0, bf1, br1);
    // Layer 2
    sgemm_kernel<<<g8, 256>>>(0, W2, 2, MROWS, COLS4H, 256);
    scan_kernel<<<512, 256>>>(1, bf2, br2);
    // Layer 3
    sgemm_kernel<<<g8, 256>>>(1, W3, 2, MROWS, COLS4H, 256);
    scan_kernel<<<512, 256>>>(0, bf3, br3);

    // ConvTranspose as GEMM: P = h4 (g_hA) @ convW(256x512) -> g_U
    sgemm_kernel<<<g4, 256>>>(0, convW, 2, MROWS, 512, 256);

    // Gather + bias + residual
    dim3 gg(CC, NN);
    gather_kernel<<<gg, 128>>>(convb, out);
}

// round 3
// speedup vs baseline: 2.2827x; 2.2827x over previous
#include <cuda_runtime.h>
#include <cuda_bf16.h>
#include <cstdint>

// Problem constants
#define CC 64
#define TT 128
#define FF 128
#define HH 128
#define LL 121          // F - K + 1
#define NN 512          // B*T
#define DH 256          // 2*H
#define MROWS 61952     // L*N
#define COLS4H 1024     // 2*4H

// ---------------------------------------------------------------------------
// Scratch (static device allocations - allowed)
// ---------------------------------------------------------------------------
__device__ float g_xn[4194304];                 // (B,C,T,F) normed input (fp32)
__device__ float g_U[63438848];                 // (L*N, 1024) GEMM out / P buffer
__device__ __nv_bfloat16 g_A0hi[31719424];      // (L*N, 512) unfold hi
__device__ __nv_bfloat16 g_A0lo[31719424];      // (L*N, 512) unfold lo
__device__ __nv_bfloat16 g_hhi[15859712];       // (L*N, 256) scan output hi
__device__ __nv_bfloat16 g_hlo[15859712];       // (L*N, 256) scan output lo
__device__ __nv_bfloat16 g_Bhi[1441792];        // transposed weights hi [n*K+k]
__device__ __nv_bfloat16 g_Blo[1441792];        // transposed weights lo

// ---------------------------------------------------------------------------
// PTX helpers (base sm_103-compatible: cp.async / ldmatrix / mma.sync)
// ---------------------------------------------------------------------------
__device__ __forceinline__ uint32_t smem_u32(const void* p) {
    return (uint32_t)__cvta_generic_to_shared(p);
}
__device__ __forceinline__ void cpa16(uint32_t s, const void* g) {
    asm volatile("cp.async.cg.shared.global [%0], [%1], 16;" :: "r"(s), "l"(g));
}
__device__ __forceinline__ void cp_commit() {
    asm volatile("cp.async.commit_group;" ::: "memory");
}
__device__ __forceinline__ void cp_wait2() {
    asm volatile("cp.async.wait_group 2;" ::: "memory");
}
__device__ __forceinline__ void ldm4(uint32_t* r, uint32_t a) {
    asm volatile("ldmatrix.sync.aligned.m8n8.x4.shared.b16 {%0,%1,%2,%3}, [%4];"
        : "=r"(r[0]), "=r"(r[1]), "=r"(r[2]), "=r"(r[3]) : "r"(a));
}
__device__ __forceinline__ void mma16816(float* d, const uint32_t* a, const uint32_t* b) {
    asm volatile(
        "mma.sync.aligned.m16n8k16.row.col.f32.bf16.bf16.f32 "
        "{%0,%1,%2,%3}, {%4,%5,%6,%7}, {%8,%9}, {%0,%1,%2,%3};"
        : "+f"(d[0]), "+f"(d[1]), "+f"(d[2]), "+f"(d[3])
        : "r"(a[0]), "r"(a[1]), "r"(a[2]), "r"(a[3]), "r"(b[0]), "r"(b[1]));
}
// smem tile layout: 128 rows x 4 16B-units, unit swizzled by (row>>1)&3
__device__ __forceinline__ uint32_t soff(int row, int u) {
    return (uint32_t)((row * 4 + (u ^ ((row >> 1) & 3))) << 4);
}

// ---------------------------------------------------------------------------
// 1) Channel norm over C
// ---------------------------------------------------------------------------
__global__ __launch_bounds__(256) void norm_kernel(
    const float* __restrict__ x, const float* __restrict__ gamma,
    const float* __restrict__ beta)
{
    int idx = blockIdx.x * 256 + threadIdx.x;   // B*T*F = 65536
    int f = idx & 127;
    int t = (idx >> 7) & 127;
    int b = idx >> 14;
    long base = ((long)b * CC * TT * FF) + (long)t * FF + f;
    const float* xp = x + base;
    float v[CC];
    float s = 0.f;
#pragma unroll
    for (int c = 0; c < CC; ++c) { v[c] = xp[(long)c * TT * FF]; s += v[c]; }
    float mu = s * (1.f / 64.f);
    float vs = 0.f;
#pragma unroll
    for (int c = 0; c < CC; ++c) { float d = v[c] - mu; vs += d * d; }
    float inv = rsqrtf(vs * (1.f / 64.f) + 1e-8f);
    float* op = g_xn + base;
#pragma unroll
    for (int c = 0; c < CC; ++c)
        op[(long)c * TT * FF] = gamma[c] * (v[c] - mu) * inv + beta[c];
}

// ---------------------------------------------------------------------------
// 2) Unfold -> A0 hi/lo (bf16 split)
// ---------------------------------------------------------------------------
__global__ __launch_bounds__(256) void unfold_kernel()
{
    long o = (long)blockIdx.x * 256 + threadIdx.x;
    if (o >= 31719424L) return;
    int col = (int)(o & 511);
    int k = col & 7;
    int c = col >> 3;
    long row = o >> 9;
    int n = (int)(row & 511);
    int l = (int)(row >> 9);
    int b = n >> 7;
    int t = n & 127;
    float v = g_xn[(((long)(b * CC + c) * TT + t) << 7) + l + k];
    __nv_bfloat16 hi = __float2bfloat16(v);
    g_A0hi[o] = hi;
    g_A0lo[o] = __float2bfloat16(v - __bfloat162float(hi));
}

// ---------------------------------------------------------------------------
// 3) Weight transpose + bf16 split: Bt[n*K+k] = W[k*Nfull+n]
// ---------------------------------------------------------------------------
__global__ __launch_bounds__(256) void wsplit_kernel(
    const float* __restrict__ W, long wOff, int Ktot, int Nfull)
{
    long idx = (long)blockIdx.x * 256 + threadIdx.x;
    if (idx >= (long)Ktot * Nfull) return;
    int n = (int)(idx / Ktot);
    int k = (int)(idx % Ktot);
    float v = W[(long)k * Nfull + n];
    __nv_bfloat16 hi = __float2bfloat16(v);
    g_Bhi[wOff + idx] = hi;
    g_Blo[wOff + idx] = __float2bfloat16(v - __bfloat162float(hi));
}

// ---------------------------------------------------------------------------
// 4) mma.sync GEMM: C(M x N) = split-bf16( A(M x Ktot) * Bt^T ), fp32 out.
//    CTA tile 128x128, BK=32, 8 warps (warp tile 64x32), 4-stage cp.async.
//    Products: Ahi*Bhi + Ahi*Blo + Alo*Bhi (bf16x3).
// ---------------------------------------------------------------------------
#define STB 32768                  // per-stage: Ahi 8K | Alo 8K | Bhi 8K | Blo 8K
#define SMEM_DYN (4 * STB)

__global__ __launch_bounds__(256) void mma_gemm(
    int aId, long wOff, int Ktot, int Nstride)
{
    extern __shared__ __align__(16) char sm[];
    const __nv_bfloat16* __restrict__ Ahp = aId ? g_hhi : g_A0hi;
    const __nv_bfloat16* __restrict__ Alp = aId ? g_hlo : g_A0lo;
    const __nv_bfloat16* __restrict__ Bhp = g_Bhi + wOff;
    const __nv_bfloat16* __restrict__ Blp = g_Blo + wOff;

    const int tid = threadIdx.x;
    const int wid = tid >> 5;
    const int lane = tid & 31;
    const long bm = (long)blockIdx.y * 128;
    const long bn = (long)blockIdx.x * 128;
    const int wm = (wid & 1) * 64;
    const int wn = (wid >> 1) * 32;
    const int KT = Ktot >> 5;

    // global->smem load mapping (each thread: 2 rows per sub-tile)
    const int lu = tid & 3;
    const int lr = tid >> 2;                     // 0..63
    const uint32_t so1 = soff(lr, lu);
    const uint32_t so2 = soff(lr + 64, lu);
    const long gaoff1 = (bm + lr) * (long)Ktot + lu * 8;
    const long gaoff2 = gaoff1 + 64L * Ktot;
    const long gboff1 = (bn + lr) * (long)Ktot + lu * 8;
    const long gboff2 = gboff1 + 64L * Ktot;

    // ldmatrix lane mapping
    const int grp = lane >> 3;
    const int l8 = lane & 7;
    const int arow0 = wm + (grp & 1) * 8 + l8;   // + mf*16
    const int auadd = grp >> 1;                  // + ks*2
    const int brow0 = wn + (grp >> 1) * 8 + l8;  // + np*16
    const int buadd = grp & 1;                   // + ks*2

    float acc[4][4][4];
#pragma unroll
    for (int i = 0; i < 4; ++i)
#pragma unroll
        for (int j = 0; j < 4; ++j)
#pragma unroll
            for (int q = 0; q < 4; ++q) acc[i][j][q] = 0.f;

    auto issue = [&](int kt) {
        uint32_t sa = smem_u32(sm + (kt & 3) * STB);
        long k0 = (long)kt * 32;
        cpa16(sa + so1,          Ahp + gaoff1 + k0);
        cpa16(sa + so2,          Ahp + gaoff2 + k0);
        cpa16(sa + 8192  + so1,  Alp + gaoff1 + k0);
        cpa16(sa + 8192  + so2,  Alp + gaoff2 + k0);
        cpa16(sa + 16384 + so1,  Bhp + gboff1 + k0);
        cpa16(sa + 16384 + so2,  Bhp + gboff2 + k0);
        cpa16(sa + 24576 + so1,  Blp + gboff1 + k0);
        cpa16(sa + 24576 + so2,  Blp + gboff2 + k0);
    };

    auto compute = [&](int kt) {
        uint32_t sAh = smem_u32(sm + (kt & 3) * STB);
        uint32_t sAl = sAh + 8192;
        uint32_t sBh = sAh + 16384;
        uint32_t sBl = sAh + 24576;
#pragma unroll
        for (int ks = 0; ks < 2; ++ks) {
            uint32_t ahi[4][4], alo[4][4], bhi[2][4], blo[2][4];
#pragma unroll
            for (int mf = 0; mf < 4; ++mf) {
                uint32_t o = soff(arow0 + mf * 16, ks * 2 + auadd);
                ldm4(ahi[mf], sAh + o);
                ldm4(alo[mf], sAl + o);
            }
#pragma unroll
            for (int np = 0; np < 2; ++np) {
                uint32_t o = soff(brow0 + np * 16, ks * 2 + buadd);
                ldm4(bhi[np], sBh + o);
                ldm4(blo[np], sBl + o);
            }
#pragma unroll
            for (int mf = 0; mf < 4; ++mf)
#pragma unroll
                for (int nf = 0; nf < 4; ++nf) {
                    const uint32_t* bh2 = &bhi[nf >> 1][(nf & 1) * 2];
                    const uint32_t* bl2 = &blo[nf >> 1][(nf & 1) * 2];
                    mma16816(acc[mf][nf], ahi[mf], bh2);
                    mma16816(acc[mf][nf], ahi[mf], bl2);
                    mma16816(acc[mf][nf], alo[mf], bh2);
                }
        }
    };

    issue(0); cp_commit();
    issue(1); cp_commit();
    issue(2); cp_commit();
    cp_wait2();
    __syncthreads();

    for (int kt = 0; kt < KT; ++kt) {
        if (kt + 3 < KT) issue(kt + 3);
        cp_commit();
        compute(kt);
        cp_wait2();
        __syncthreads();
    }

    // Epilogue: c0,c1 at (row, col), c2,c3 at (row+8, col)
    const int er = lane >> 2;
    const int ec = (lane & 3) * 2;
#pragma unroll
    for (int mf = 0; mf < 4; ++mf)
#pragma unroll
        for (int nf = 0; nf < 4; ++nf) {
            float* p = g_U + (bm + wm + mf * 16 + er) * (long)Nstride
                           + bn + wn + nf * 8 + ec;
            *(float2*)p = make_float2(acc[mf][nf][0], acc[mf][nf][1]);
            *(float2*)(p + 8L * Nstride) = make_float2(acc[mf][nf][2], acc[mf][nf][3]);
        }
}

// ---------------------------------------------------------------------------
// 5) SRU scan: U (L*N,1024) -> h hi/lo (L*N,256)
// ---------------------------------------------------------------------------
__global__ __launch_bounds__(256) void scan_kernel(
    const float* __restrict__ bf, const float* __restrict__ br)
{
    const float* __restrict__ U = g_U;

    int t = blockIdx.x * 256 + threadIdx.x;   // 131072 lanes
    int hidx = t & 127;
    int n = (t >> 7) & 511;
    int dir = t >> 16;

    float bfv = bf[dir * HH + hidx];
    float brv = br[dir * HH + hidx];

    long ubase = (long)n * COLS4H + dir * 512 + hidx;
    long obase = (long)n * DH + dir * HH + hidx;

    float c = 0.f;
    if (dir == 0) {
        for (int l = 0; l < LL; ++l) {
            const float* u = U + ubase + (long)l * NN * COLS4H;
            float z = u[0], fg = u[128], r = u[256], hp = u[384];
            fg = 1.f / (1.f + __expf(-(fg + bfv)));
            r = 1.f / (1.f + __expf(-(r + brv)));
            c = fg * c + (1.f - fg) * z;
            float o = r * c + (1.f - r) * hp;
            __nv_bfloat16 hi = __float2bfloat16(o);
            long oi = obase + (long)l * NN * DH;
            g_hhi[oi] = hi;
            g_hlo[oi] = __float2bfloat16(o - __bfloat162float(hi));
        }
    } else {
        for (int l = LL - 1; l >= 0; --l) {
            const float* u = U + ubase + (long)l * NN * COLS4H;
            float z = u[0], fg = u[128], r = u[256], hp = u[384];
            fg = 1.f / (1.f + __expf(-(fg + bfv)));
            r = 1.f / (1.f + __expf(-(r + brv)));
            c = fg * c + (1.f - fg) * z;
            float o = r * c + (1.f - r) * hp;
            __nv_bfloat16 hi = __float2bfloat16(o);
            long oi = obase + (long)l * NN * DH;
            g_hhi[oi] = hi;
            g_hlo[oi] = __float2bfloat16(o - __bfloat162float(hi));
        }
    }
}

// ---------------------------------------------------------------------------
// 6) ConvTranspose gather + bias + residual
// ---------------------------------------------------------------------------
__global__ __launch_bounds__(128) void gather_kernel(
    const float* __restrict__ convb, float* __restrict__ out)
{
    __shared__ float sP[LL * 9 + 8];
    int c = blockIdx.x;
    int n = blockIdx.y;
    int f = threadIdx.x;

    for (int idx = f; idx < LL * 8; idx += 128) {
        int l = idx >> 3, j = idx & 7;
        sP[l * 9 + j] = g_U[((long)(l * NN + n)) * 512 + c * 8 + j];
    }
    __syncthreads();

    float acc = convb[c];
#pragma unroll
    for (int k = 0; k < 8; ++k) {
        int l = f - k;
        if (l >= 0 && l < LL) acc += sP[l * 9 + k];
    }
    int b = n >> 7, t = n & 127;
    long oi = (((long)(b * CC + c) * TT + t) << 7) + f;
    out[oi] = acc + g_xn[oi];
}

// ---------------------------------------------------------------------------
// Launch
// ---------------------------------------------------------------------------
extern "C" void kernel_launch(void* const* d_in, const int* in_sizes, int n_in,
                              void* d_out, int out_size)
{
    const float* x     = (const float*)d_in[0];
    const float* gamma = (const float*)d_in[1];
    const float* beta  = (const float*)d_in[2];
    const float* W0  = (const float*)d_in[3];
    const float* bf0 = (const float*)d_in[4];
    const float* br0 = (const float*)d_in[5];
    const float* W1  = (const float*)d_in[6];
    const float* bf1 = (const float*)d_in[7];
    const float* br1 = (const float*)d_in[8];
    const float* W2  = (const float*)d_in[9];
    const float* bf2 = (const float*)d_in[10];
    const float* br2 = (const float*)d_in[11];
    const float* W3  = (const float*)d_in[12];
    const float* bf3 = (const float*)d_in[13];
    const float* br3 = (const float*)d_in[14];
    const float* convW = (const float*)d_in[15];
    const float* convb = (const float*)d_in[16];
    float* out = (float*)d_out;

    cudaFuncSetAttribute(mma_gemm, cudaFuncAttributeMaxDynamicSharedMemorySize,
                         SMEM_DYN);

    // Weight transpose + split (tiny)
    wsplit_kernel<<<2048, 256>>>(W0, 0L, 512, 1024);
    wsplit_kernel<<<1024, 256>>>(W1, 524288L, 256, 1024);
    wsplit_kernel<<<1024, 256>>>(W2, 786432L, 256, 1024);
    wsplit_kernel<<<1024, 256>>>(W3, 1048576L, 256, 1024);
    wsplit_kernel<<<512, 256>>>(convW, 1310720L, 256, 512);

    norm_kernel<<<256, 256>>>(x, gamma, beta);
    unfold_kernel<<<123904, 256>>>();

    dim3 gU(8, 484);   // N=1024: 8 N-tiles of 128
    dim3 gP(4, 484);   // N=512:  4 N-tiles of 128

    // Layer 0 (K=512)
    mma_gemm<<<gU, 256, SMEM_DYN>>>(0, 0L, 512, 1024);
    scan_kernel<<<512, 256>>>(bf0, br0);
    // Layers 1-3 (K=256)
    mma_gemm<<<gU, 256, SMEM_DYN>>>(1, 524288L, 256, 1024);
    scan_kernel<<<512, 256>>>(bf1, br1);
    mma_gemm<<<gU, 256, SMEM_DYN>>>(1, 786432L, 256, 1024);
    scan_kernel<<<512, 256>>>(bf2, br2);
    mma_gemm<<<gU, 256, SMEM_DYN>>>(1, 1048576L, 256, 1024);
    scan_kernel<<<512, 256>>>(bf3, br3);

    // ConvTranspose as GEMM: P = h4 @ convW^T  (M x 512, K=256)
    mma_gemm<<<gP, 256, SMEM_DYN>>>(1, 1310720L, 256, 512);

    dim3 gg(CC, NN);
    gather_kernel<<<gg, 128>>>(convb, out);
}

// round 4
// speedup vs baseline: 2.5438x; 1.1144x over previous
#include <cuda_runtime.h>
#include <cuda_bf16.h>
#include <cstdint>

// Problem constants
#define CC 64
#define TT 128
#define FF 128
#define HH 128
#define LL 121          // F - K + 1
#define NN 512          // B*T
#define DH 256          // 2*H
#define MROWS 61952     // L*N
#define COLS4H 1024     // 2*4H

// ---------------------------------------------------------------------------
// Scratch (static device allocations - allowed)
// ---------------------------------------------------------------------------
__device__ float g_xn[4194304];                 // (B,C,T,F) normed input (fp32)
__device__ float g_U[63438848];                 // (L*N, 1024) GEMM out / P buffer
__device__ __nv_bfloat16 g_A0hi[31719424];      // (L*N, 512) unfold hi
__device__ __nv_bfloat16 g_A0lo[31719424];      // (L*N, 512) unfold lo
__device__ __nv_bfloat16 g_hhi[15859712];       // (L*N, 256) scan output hi
__device__ __nv_bfloat16 g_hlo[15859712];       // (L*N, 256) scan output lo
__device__ __nv_bfloat16 g_Bhi[1441792];        // transposed weights hi [n*K+k]
__device__ __nv_bfloat16 g_Blo[1441792];        // transposed weights lo

// ---------------------------------------------------------------------------
// PTX helpers (base sm_103-compatible: cp.async / ldmatrix / mma.sync)
// ---------------------------------------------------------------------------
__device__ __forceinline__ uint32_t smem_u32(const void* p) {
    return (uint32_t)__cvta_generic_to_shared(p);
}
__device__ __forceinline__ void cpa16(uint32_t s, const void* g) {
    asm volatile("cp.async.cg.shared.global [%0], [%1], 16;" :: "r"(s), "l"(g));
}
__device__ __forceinline__ void cp_commit() {
    asm volatile("cp.async.commit_group;" ::: "memory");
}
__device__ __forceinline__ void cp_wait2() {
    asm volatile("cp.async.wait_group 2;" ::: "memory");
}
__device__ __forceinline__ void ldm4(uint32_t* r, uint32_t a) {
    asm volatile("ldmatrix.sync.aligned.m8n8.x4.shared.b16 {%0,%1,%2,%3}, [%4];"
        : "=r"(r[0]), "=r"(r[1]), "=r"(r[2]), "=r"(r[3]) : "r"(a));
}
__device__ __forceinline__ void mma16816(float* d, const uint32_t* a, const uint32_t* b) {
    asm volatile(
        "mma.sync.aligned.m16n8k16.row.col.f32.bf16.bf16.f32 "
        "{%0,%1,%2,%3}, {%4,%5,%6,%7}, {%8,%9}, {%0,%1,%2,%3};"
        : "+f"(d[0]), "+f"(d[1]), "+f"(d[2]), "+f"(d[3])
        : "r"(a[0]), "r"(a[1]), "r"(a[2]), "r"(a[3]), "r"(b[0]), "r"(b[1]));
}
// smem tile layout: rows x 4 16B-units, unit swizzled by (row>>1)&3
__device__ __forceinline__ uint32_t soff(int row, int u) {
    return (uint32_t)((row * 4 + (u ^ ((row >> 1) & 3))) << 4);
}

// ---------------------------------------------------------------------------
// 1) Channel norm over C
// ---------------------------------------------------------------------------
__global__ __launch_bounds__(256) void norm_kernel(
    const float* __restrict__ x, const float* __restrict__ gamma,
    const float* __restrict__ beta)
{
    int idx = blockIdx.x * 256 + threadIdx.x;   // B*T*F = 65536
    int f = idx & 127;
    int t = (idx >> 7) & 127;
    int b = idx >> 14;
    long base = ((long)b * CC * TT * FF) + (long)t * FF + f;
    const float* xp = x + base;
    float v[CC];
    float s = 0.f;
#pragma unroll
    for (int c = 0; c < CC; ++c) { v[c] = xp[(long)c * TT * FF]; s += v[c]; }
    float mu = s * (1.f / 64.f);
    float vs = 0.f;
#pragma unroll
    for (int c = 0; c < CC; ++c) { float d = v[c] - mu; vs += d * d; }
    float inv = rsqrtf(vs * (1.f / 64.f) + 1e-8f);
    float* op = g_xn + base;
#pragma unroll
    for (int c = 0; c < CC; ++c)
        op[(long)c * TT * FF] = gamma[c] * (v[c] - mu) * inv + beta[c];
}

// ---------------------------------------------------------------------------
// 2) Unfold -> A0 hi/lo (bf16 split)
// ---------------------------------------------------------------------------
__global__ __launch_bounds__(256) void unfold_kernel()
{
    long o = (long)blockIdx.x * 256 + threadIdx.x;
    if (o >= 31719424L) return;
    int col = (int)(o & 511);
    int k = col & 7;
    int c = col >> 3;
    long row = o >> 9;
    int n = (int)(row & 511);
    int l = (int)(row >> 9);
    int b = n >> 7;
    int t = n & 127;
    float v = g_xn[(((long)(b * CC + c) * TT + t) << 7) + l + k];
    __nv_bfloat16 hi = __float2bfloat16(v);
    g_A0hi[o] = hi;
    g_A0lo[o] = __float2bfloat16(v - __bfloat162float(hi));
}

// ---------------------------------------------------------------------------
// 3) Weight transpose + bf16 split: Bt[n*K+k] = W[k*Nfull+n]
// ---------------------------------------------------------------------------
__global__ __launch_bounds__(256) void wsplit_kernel(
    const float* __restrict__ W, long wOff, int Ktot, int Nfull)
{
    long idx = (long)blockIdx.x * 256 + threadIdx.x;
    if (idx >= (long)Ktot * Nfull) return;
    int n = (int)(idx / Ktot);
    int k = (int)(idx % Ktot);
    float v = W[(long)k * Nfull + n];
    __nv_bfloat16 hi = __float2bfloat16(v);
    g_Bhi[wOff + idx] = hi;
    g_Blo[wOff + idx] = __float2bfloat16(v - __bfloat162float(hi));
}

// ---------------------------------------------------------------------------
// 4) mma.sync GEMM: C(M x N) = split-bf16( A(M x Ktot) * Bt^T ), fp32 out.
//    CTA tile 128x256, BK=32, 8 warps (warp tile 64x64), 4-stage cp.async.
//    Products: Ahi*Bhi + Ahi*Blo + Alo*Bhi (bf16x3).
//    Stage: Ahi 8K | Alo 8K | Bhi 16K | Blo 16K = 48K
// ---------------------------------------------------------------------------
#define STB 49152
#define SMEM_DYN (4 * STB)

__global__ __launch_bounds__(256, 1) void mma_gemm(
    int aId, long wOff, int Ktot, int Nstride)
{
    extern __shared__ __align__(16) char sm[];
    const __nv_bfloat16* __restrict__ Ahp = aId ? g_hhi : g_A0hi;
    const __nv_bfloat16* __restrict__ Alp = aId ? g_hlo : g_A0lo;
    const __nv_bfloat16* __restrict__ Bhp = g_Bhi + wOff;
    const __nv_bfloat16* __restrict__ Blp = g_Blo + wOff;

    const int tid = threadIdx.x;
    const int wid = tid >> 5;
    const int lane = tid & 31;
    const long bm = (long)blockIdx.y * 128;
    const long bn = (long)blockIdx.x * 256;
    const int wm = (wid & 1) * 64;
    const int wn = (wid >> 1) * 64;
    const int KT = Ktot >> 5;

    // global->smem load mapping
    const int lu = tid & 3;
    const int lr = tid >> 2;                     // 0..63
    const uint32_t so1 = soff(lr, lu);
    const uint32_t so2 = soff(lr + 64, lu);
    const uint32_t so3 = soff(lr + 128, lu);
    const uint32_t so4 = soff(lr + 192, lu);
    const long gaoff1 = (bm + lr) * (long)Ktot + lu * 8;
    const long gaoff2 = gaoff1 + 64L * Ktot;
    const long gboff1 = (bn + lr) * (long)Ktot + lu * 8;
    const long gboff2 = gboff1 + 64L * Ktot;
    const long gboff3 = gboff1 + 128L * Ktot;
    const long gboff4 = gboff1 + 192L * Ktot;

    // ldmatrix lane mapping
    const int grp = lane >> 3;
    const int l8 = lane & 7;
    const int arow0 = wm + (grp & 1) * 8 + l8;   // + mf*16
    const int auadd = grp >> 1;                  // + ks*2
    const int brow0 = wn + (grp >> 1) * 8 + l8;  // + np*16
    const int buadd = grp & 1;                   // + ks*2

    float acc[4][8][4];
#pragma unroll
    for (int i = 0; i < 4; ++i)
#pragma unroll
        for (int j = 0; j < 8; ++j)
#pragma unroll
            for (int q = 0; q < 4; ++q) acc[i][j][q] = 0.f;

    auto issue = [&](int kt) {
        uint32_t sa = smem_u32(sm + (kt & 3) * STB);
        long k0 = (long)kt * 32;
        cpa16(sa + so1,          Ahp + gaoff1 + k0);
        cpa16(sa + so2,          Ahp + gaoff2 + k0);
        cpa16(sa + 8192  + so1,  Alp + gaoff1 + k0);
        cpa16(sa + 8192  + so2,  Alp + gaoff2 + k0);
        cpa16(sa + 16384 + so1,  Bhp + gboff1 + k0);
        cpa16(sa + 16384 + so2,  Bhp + gboff2 + k0);
        cpa16(sa + 16384 + so3,  Bhp + gboff3 + k0);
        cpa16(sa + 16384 + so4,  Bhp + gboff4 + k0);
        cpa16(sa + 32768 + so1,  Blp + gboff1 + k0);
        cpa16(sa + 32768 + so2,  Blp + gboff2 + k0);
        cpa16(sa + 32768 + so3,  Blp + gboff3 + k0);
        cpa16(sa + 32768 + so4,  Blp + gboff4 + k0);
    };

    auto compute = [&](int kt) {
        uint32_t sAh = smem_u32(sm + (kt & 3) * STB);
        uint32_t sAl = sAh + 8192;
        uint32_t sBh = sAh + 16384;
        uint32_t sBl = sAh + 32768;
#pragma unroll
        for (int ks = 0; ks < 2; ++ks) {
            uint32_t ahi[4][4], alo[4][4], bhi[4][4], blo[4][4];
#pragma unroll
            for (int mf = 0; mf < 4; ++mf) {
                uint32_t o = soff(arow0 + mf * 16, ks * 2 + auadd);
                ldm4(ahi[mf], sAh + o);
                ldm4(alo[mf], sAl + o);
            }
#pragma unroll
            for (int np = 0; np < 4; ++np) {
                uint32_t o = soff(brow0 + np * 16, ks * 2 + buadd);
                ldm4(bhi[np], sBh + o);
                ldm4(blo[np], sBl + o);
            }
#pragma unroll
            for (int mf = 0; mf < 4; ++mf)
#pragma unroll
                for (int nf = 0; nf < 8; ++nf) {
                    const uint32_t* bh2 = &bhi[nf >> 1][(nf & 1) * 2];
                    const uint32_t* bl2 = &blo[nf >> 1][(nf & 1) * 2];
                    mma16816(acc[mf][nf], ahi[mf], bh2);
                    mma16816(acc[mf][nf], ahi[mf], bl2);
                    mma16816(acc[mf][nf], alo[mf], bh2);
                }
        }
    };

    issue(0); cp_commit();
    issue(1); cp_commit();
    issue(2); cp_commit();
    cp_wait2();
    __syncthreads();

    for (int kt = 0; kt < KT; ++kt) {
        if (kt + 3 < KT) issue(kt + 3);
        cp_commit();
        compute(kt);
        cp_wait2();
        __syncthreads();
    }

    // Epilogue: c0,c1 at (row, col), c2,c3 at (row+8, col)
    const int er = lane >> 2;
    const int ec = (lane & 3) * 2;
#pragma unroll
    for (int mf = 0; mf < 4; ++mf)
#pragma unroll
        for (int nf = 0; nf < 8; ++nf) {
            float* p = g_U + (bm + wm + mf * 16 + er) * (long)Nstride
                           + bn + wn + nf * 8 + ec;
            *(float2*)p = make_float2(acc[mf][nf][0], acc[mf][nf][1]);
            *(float2*)(p + 8L * Nstride) = make_float2(acc[mf][nf][2], acc[mf][nf][3]);
        }
}

// ---------------------------------------------------------------------------
// 5) SRU scan: U (L*N,1024) -> h hi/lo (L*N,256), prefetched
// ---------------------------------------------------------------------------
__global__ __launch_bounds__(256) void scan_kernel(
    const float* __restrict__ bf, const float* __restrict__ br)
{
    const float* __restrict__ U = g_U;

    int t = blockIdx.x * 256 + threadIdx.x;   // 131072 lanes
    int hidx = t & 127;
    int n = (t >> 7) & 511;
    int dir = t >> 16;

    float bfv = bf[dir * HH + hidx];
    float brv = br[dir * HH + hidx];

    const long ustep = (long)NN * COLS4H;
    const long ostep = (long)NN * DH;
    long ustride = dir ? -ustep : ustep;
    long ostride = dir ? -ostep : ostep;
    const float* u = U + (long)n * COLS4H + dir * 512 + hidx
                     + (dir ? (LL - 1) * ustep : 0);
    long oi = (long)n * DH + dir * HH + hidx + (dir ? (LL - 1) * ostep : 0);

    float z = u[0], fg = u[128], r = u[256], hp = u[384];
    float c = 0.f;
    for (int l = 0; l < LL; ++l) {
        const float* un = u + ustride;
        float zn = 0.f, fn = 0.f, rn = 0.f, hn = 0.f;
        if (l + 1 < LL) { zn = un[0]; fn = un[128]; rn = un[256]; hn = un[384]; }
        float fs = 1.f / (1.f + __expf(-(fg + bfv)));
        float rs = 1.f / (1.f + __expf(-(r + brv)));
        c = fs * c + (1.f - fs) * z;
        float o = rs * c + (1.f - rs) * hp;
        __nv_bfloat16 hi = __float2bfloat16(o);
        g_hhi[oi] = hi;
        g_hlo[oi] = __float2bfloat16(o - __bfloat162float(hi));
        u = un; z = zn; fg = fn; r = rn; hp = hn; oi += ostride;
    }
}

// ---------------------------------------------------------------------------
// 6) ConvTranspose gather + bias + residual
// ---------------------------------------------------------------------------
__global__ __launch_bounds__(128) void gather_kernel(
    const float* __restrict__ convb, float* __restrict__ out)
{
    __shared__ float sP[LL * 9 + 8];
    int c = blockIdx.x;
    int n = blockIdx.y;
    int f = threadIdx.x;

    for (int idx = f; idx < LL * 8; idx += 128) {
        int l = idx >> 3, j = idx & 7;
        sP[l * 9 + j] = g_U[((long)(l * NN + n)) * 512 + c * 8 + j];
    }
    __syncthreads();

    float acc = convb[c];
#pragma unroll
    for (int k = 0; k < 8; ++k) {
        int l = f - k;
        if (l >= 0 && l < LL) acc += sP[l * 9 + k];
    }
    int b = n >> 7, t = n & 127;
    long oi = (((long)(b * CC + c) * TT + t) << 7) + f;
    out[oi] = acc + g_xn[oi];
}

// ---------------------------------------------------------------------------
// Launch
// ---------------------------------------------------------------------------
extern "C" void kernel_launch(void* const* d_in, const int* in_sizes, int n_in,
                              void* d_out, int out_size)
{
    const float* x     = (const float*)d_in[0];
    const float* gamma = (const float*)d_in[1];
    const float* beta  = (const float*)d_in[2];
    const float* W0  = (const float*)d_in[3];
    const float* bf0 = (const float*)d_in[4];
    const float* br0 = (const float*)d_in[5];
    const float* W1  = (const float*)d_in[6];
    const float* bf1 = (const float*)d_in[7];
    const float* br1 = (const float*)d_in[8];
    const float* W2  = (const float*)d_in[9];
    const float* bf2 = (const float*)d_in[10];
    const float* br2 = (const float*)d_in[11];
    const float* W3  = (const float*)d_in[12];
    const float* bf3 = (const float*)d_in[13];
    const float* br3 = (const float*)d_in[14];
    const float* convW = (const float*)d_in[15];
    const float* convb = (const float*)d_in[16];
    float* out = (float*)d_out;

    cudaFuncSetAttribute(mma_gemm, cudaFuncAttributeMaxDynamicSharedMemorySize,
                         SMEM_DYN);

    // Weight transpose + split (tiny)
    wsplit_kernel<<<2048, 256>>>(W0, 0L, 512, 1024);
    wsplit_kernel<<<1024, 256>>>(W1, 524288L, 256, 1024);
    wsplit_kernel<<<1024, 256>>>(W2, 786432L, 256, 1024);
    wsplit_kernel<<<1024, 256>>>(W3, 1048576L, 256, 1024);
    wsplit_kernel<<<512, 256>>>(convW, 1310720L, 256, 512);

    norm_kernel<<<256, 256>>>(x, gamma, beta);
    unfold_kernel<<<123904, 256>>>();

    dim3 gU(4, 484);   // N=1024: 4 N-tiles of 256
    dim3 gP(2, 484);   // N=512:  2 N-tiles of 256

    // Layer 0 (K=512)
    mma_gemm<<<gU, 256, SMEM_DYN>>>(0, 0L, 512, 1024);
    scan_kernel<<<512, 256>>>(bf0, br0);
    // Layers 1-3 (K=256)
    mma_gemm<<<gU, 256, SMEM_DYN>>>(1, 524288L, 256, 1024);
    scan_kernel<<<512, 256>>>(bf1, br1);
    mma_gemm<<<gU, 256, SMEM_DYN>>>(1, 786432L, 256, 1024);
    scan_kernel<<<512, 256>>>(bf2, br2);
    mma_gemm<<<gU, 256, SMEM_DYN>>>(1, 1048576L, 256, 1024);
    scan_kernel<<<512, 256>>>(bf3, br3);

    // ConvTranspose as GEMM: P = h4 @ convW^T  (M x 512, K=256)
    mma_gemm<<<gP, 256, SMEM_DYN>>>(1, 1310720L, 256, 512);

    dim3 gg(CC, NN);
    gather_kernel<<<gg, 128>>>(convb, out);
}

// round 5
// speedup vs baseline: 3.2247x; 1.2677x over previous
#include <cuda_runtime.h>
#include <cuda_bf16.h>
#include <cstdint>

// Problem constants
#define CC 64
#define TT 128
#define FF 128
#define HH 128
#define LL 121          // F - K + 1
#define NN 512          // B*T
#define DH 256          // 2*H
#define MROWS 61952     // L*N
#define COLS4H 1024     // 2*4H

// ---------------------------------------------------------------------------
// Scratch (static device allocations - allowed)
// ---------------------------------------------------------------------------
__device__ float g_xn[4194304];     // (B,C,T,F) normed input (fp32)
__device__ float g_U[63438848];     // (L*N, 1024) GEMM out / P buffer
__device__ float g_A0[31719424];    // (L*N, 512) unfold, tf32-rounded
__device__ float g_h[15859712];     // (L*N, 256) scan output, tf32-rounded
__device__ float g_Bt[1441792];     // transposed weights [n*K+k], tf32-rounded

// ---------------------------------------------------------------------------
// PTX helpers (base sm_103-compatible: cp.async / ldmatrix / mma.sync tf32)
// ---------------------------------------------------------------------------
__device__ __forceinline__ uint32_t smem_u32(const void* p) {
    return (uint32_t)__cvta_generic_to_shared(p);
}
__device__ __forceinline__ void cpa16(uint32_t s, const void* g) {
    asm volatile("cp.async.cg.shared.global [%0], [%1], 16;" :: "r"(s), "l"(g));
}
__device__ __forceinline__ void cp_commit() {
    asm volatile("cp.async.commit_group;" ::: "memory");
}
__device__ __forceinline__ void cp_wait2() {
    asm volatile("cp.async.wait_group 2;" ::: "memory");
}
__device__ __forceinline__ void ldm4(uint32_t* r, uint32_t a) {
    asm volatile("ldmatrix.sync.aligned.m8n8.x4.shared.b16 {%0,%1,%2,%3}, [%4];"
        : "=r"(r[0]), "=r"(r[1]), "=r"(r[2]), "=r"(r[3]) : "r"(a));
}
__device__ __forceinline__ void mma_tf32(float* d, const uint32_t* a, const uint32_t* b) {
    asm volatile(
        "mma.sync.aligned.m16n8k8.row.col.f32.tf32.tf32.f32 "
        "{%0,%1,%2,%3}, {%4,%5,%6,%7}, {%8,%9}, {%0,%1,%2,%3};"
        : "+f"(d[0]), "+f"(d[1]), "+f"(d[2]), "+f"(d[3])
        : "r"(a[0]), "r"(a[1]), "r"(a[2]), "r"(a[3]), "r"(b[0]), "r"(b[1]));
}
__device__ __forceinline__ float tf32r(float v) {
    uint32_t o;
    asm("cvt.rna.tf32.f32 %0, %1;" : "=r"(o) : "f"(v));
    return __uint_as_float(o);
}
// fp32 tile: rows x 8 16B-units (32 floats/row), unit swizzled by row&7
__device__ __forceinline__ uint32_t soff32(int row, int u) {
    return (uint32_t)(((row << 3) + (u ^ (row & 7))) << 4);
}

// ---------------------------------------------------------------------------
// 1) Channel norm over C
// ---------------------------------------------------------------------------
__global__ __launch_bounds__(256) void norm_kernel(
    const float* __restrict__ x, const float* __restrict__ gamma,
    const float* __restrict__ beta)
{
    int idx = blockIdx.x * 256 + threadIdx.x;   // B*T*F = 65536
    int f = idx & 127;
    int t = (idx >> 7) & 127;
    int b = idx >> 14;
    long base = ((long)b * CC * TT * FF) + (long)t * FF + f;
    const float* xp = x + base;
    float v[CC];
    float s = 0.f;
#pragma unroll
    for (int c = 0; c < CC; ++c) { v[c] = xp[(long)c * TT * FF]; s += v[c]; }
    float mu = s * (1.f / 64.f);
    float vs = 0.f;
#pragma unroll
    for (int c = 0; c < CC; ++c) { float d = v[c] - mu; vs += d * d; }
    float inv = rsqrtf(vs * (1.f / 64.f) + 1e-8f);
    float* op = g_xn + base;
#pragma unroll
    for (int c = 0; c < CC; ++c)
        op[(long)c * TT * FF] = gamma[c] * (v[c] - mu) * inv + beta[c];
}

// ---------------------------------------------------------------------------
// 2) Unfold -> A0 (tf32-rounded fp32)
// ---------------------------------------------------------------------------
__global__ __launch_bounds__(256) void unfold_kernel()
{
    long o = (long)blockIdx.x * 256 + threadIdx.x;
    if (o >= 31719424L) return;
    int col = (int)(o & 511);
    int k = col & 7;
    int c = col >> 3;
    long row = o >> 9;
    int n = (int)(row & 511);
    int l = (int)(row >> 9);
    int b = n >> 7;
    int t = n & 127;
    g_A0[o] = tf32r(g_xn[(((long)(b * CC + c) * TT + t) << 7) + l + k]);
}

// ---------------------------------------------------------------------------
// 3) Weight transpose + tf32 round: Bt[n*K+k] = W[k*Nfull+n], 5 weights fused
// ---------------------------------------------------------------------------
__global__ __launch_bounds__(256) void wsplit_kernel(
    const float* __restrict__ W0, const float* __restrict__ W1,
    const float* __restrict__ W2, const float* __restrict__ W3,
    const float* __restrict__ Wc)
{
    long idx = (long)blockIdx.x * 256 + threadIdx.x;
    if (idx >= 1441792L) return;
    const float* W; long off; int Ktot, Nfull;
    if (idx < 524288L)        { W = W0; off = 0L;        Ktot = 512; Nfull = 1024; }
    else if (idx < 786432L)   { W = W1; off = 524288L;   Ktot = 256; Nfull = 1024; }
    else if (idx < 1048576L)  { W = W2; off = 786432L;   Ktot = 256; Nfull = 1024; }
    else if (idx < 1310720L)  { W = W3; off = 1048576L;  Ktot = 256; Nfull = 1024; }
    else                      { W = Wc; off = 1310720L;  Ktot = 256; Nfull = 512;  }
    long li = idx - off;
    int n = (int)(li / Ktot);
    int k = (int)(li % Ktot);
    g_Bt[idx] = tf32r(W[(long)k * Nfull + n]);
}

// ---------------------------------------------------------------------------
// 4) tf32 mma.sync GEMM: C(M x N) = A(M x Ktot) * Bt^T, fp32 out.
//    CTA tile 128x256, BK=32, 8 warps (warp tile 64x64), 4-stage cp.async.
//    Stage: A 16K | B 32K = 48K
// ---------------------------------------------------------------------------
#define STB 49152
#define SMEM_DYN (4 * STB)

__global__ __launch_bounds__(256, 1) void mma_gemm(
    int aId, long wOff, int Ktot, int Nstride)
{
    extern __shared__ __align__(16) char sm[];
    const float* __restrict__ Ap = aId ? g_h : g_A0;
    const float* __restrict__ Bp = g_Bt + wOff;

    const int tid = threadIdx.x;
    const int wid = tid >> 5;
    const int lane = tid & 31;
    const long bm = (long)blockIdx.y * 128;
    const long bn = (long)blockIdx.x * 256;
    const int wm = (wid & 1) * 64;
    const int wn = (wid >> 1) * 64;
    const int KT = Ktot >> 5;

    // global->smem: 16B per cpa16, 32 floats (8 units) per row
    const int lu = tid & 7;                      // unit 0..7
    const int lr = tid >> 3;                     // row 0..31
    const uint32_t soA = soff32(lr, lu);
    const long gaoff = (bm + lr) * (long)Ktot + lu * 4;
    const long gboff = (bn + lr) * (long)Ktot + lu * 4;
    const long aK = 32L * Ktot;

    // ldmatrix lane mapping
    const int arow = wm + (lane & 7) + ((lane >> 3) & 1) * 8;   // + mf*16
    const int auc  = lane >> 4;                                 // + ks*2
    const int brow = wn + (lane & 7) + ((lane >> 4) & 1) * 8;   // + nb*16
    const int buc  = (lane >> 3) & 1;                           // + ks*2

    float acc[4][8][4];
#pragma unroll
    for (int i = 0; i < 4; ++i)
#pragma unroll
        for (int j = 0; j < 8; ++j)
#pragma unroll
            for (int q = 0; q < 4; ++q) acc[i][j][q] = 0.f;

    auto issue = [&](int kt) {
        uint32_t sa = smem_u32(sm + (kt & 3) * STB);
        long k0 = (long)kt * 32;
        const float* a = Ap + gaoff + k0;
        const float* b = Bp + gboff + k0;
#pragma unroll
        for (int i = 0; i < 4; ++i)
            cpa16(sa + soff32(lr + i * 32, lu) - soA + soA, a + i * aK);
#pragma unroll
        for (int i = 0; i < 8; ++i)
            cpa16(sa + 16384 + soff32(lr + i * 32, lu), b + i * aK);
    };

    auto compute = [&](int kt) {
        uint32_t sA = smem_u32(sm + (kt & 3) * STB);
        uint32_t sB = sA + 16384;
#pragma unroll
        for (int ks = 0; ks < 4; ++ks) {
            uint32_t a[4][4], b[4][4];
#pragma unroll
            for (int mf = 0; mf < 4; ++mf)
                ldm4(a[mf], sA + soff32(arow + mf * 16, ks * 2 + auc));
#pragma unroll
            for (int nb = 0; nb < 4; ++nb)
                ldm4(b[nb], sB + soff32(brow + nb * 16, ks * 2 + buc));
#pragma unroll
            for (int mf = 0; mf < 4; ++mf)
#pragma unroll
                for (int nf = 0; nf < 8; ++nf)
                    mma_tf32(acc[mf][nf], a[mf], &b[nf >> 1][(nf & 1) * 2]);
        }
    };

    issue(0); cp_commit();
    issue(1); cp_commit();
    issue(2); cp_commit();
    cp_wait2();
    __syncthreads();

    for (int kt = 0; kt < KT; ++kt) {
        if (kt + 3 < KT) issue(kt + 3);
        cp_commit();
        compute(kt);
        cp_wait2();
        __syncthreads();
    }

    // Epilogue: c0,c1 at (row, col), c2,c3 at (row+8, col)
    const int er = lane >> 2;
    const int ec = (lane & 3) * 2;
#pragma unroll
    for (int mf = 0; mf < 4; ++mf)
#pragma unroll
        for (int nf = 0; nf < 8; ++nf) {
            float* p = g_U + (bm + wm + mf * 16 + er) * (long)Nstride
                           + bn + wn + nf * 8 + ec;
            *(float2*)p = make_float2(acc[mf][nf][0], acc[mf][nf][1]);
            *(float2*)(p + 8L * Nstride) = make_float2(acc[mf][nf][2], acc[mf][nf][3]);
        }
}

// ---------------------------------------------------------------------------
// 5) SRU scan: U (L*N,1024) -> h (L*N,256) tf32-rounded, prefetched
// ---------------------------------------------------------------------------
__global__ __launch_bounds__(256) void scan_kernel(
    const float* __restrict__ bf, const float* __restrict__ br)
{
    const float* __restrict__ U = g_U;

    int t = blockIdx.x * 256 + threadIdx.x;   // 131072 lanes
    int hidx = t & 127;
    int n = (t >> 7) & 511;
    int dir = t >> 16;

    float bfv = bf[dir * HH + hidx];
    float brv = br[dir * HH + hidx];

    const long ustep = (long)NN * COLS4H;
    const long ostep = (long)NN * DH;
    long ustride = dir ? -ustep : ustep;
    long ostride = dir ? -ostep : ostep;
    const float* u = U + (long)n * COLS4H + dir * 512 + hidx
                     + (dir ? (LL - 1) * ustep : 0);
    long oi = (long)n * DH + dir * HH + hidx + (dir ? (LL - 1) * ostep : 0);

    float z = u[0], fg = u[128], r = u[256], hp = u[384];
    float c = 0.f;
    for (int l = 0; l < LL; ++l) {
        const float* un = u + ustride;
        float zn = 0.f, fn = 0.f, rn = 0.f, hn = 0.f;
        if (l + 1 < LL) { zn = un[0]; fn = un[128]; rn = un[256]; hn = un[384]; }
        float fs = 1.f / (1.f + __expf(-(fg + bfv)));
        float rs = 1.f / (1.f + __expf(-(r + brv)));
        c = fs * c + (1.f - fs) * z;
        float o = rs * c + (1.f - rs) * hp;
        g_h[oi] = tf32r(o);
        u = un; z = zn; fg = fn; r = rn; hp = hn; oi += ostride;
    }
}

// ---------------------------------------------------------------------------
// 6) ConvTranspose gather + bias + residual
// ---------------------------------------------------------------------------
__global__ __launch_bounds__(128) void gather_kernel(
    const float* __restrict__ convb, float* __restrict__ out)
{
    __shared__ float sP[LL * 9 + 8];
    int c = blockIdx.x;
    int n = blockIdx.y;
    int f = threadIdx.x;

    for (int idx = f; idx < LL * 8; idx += 128) {
        int l = idx >> 3, j = idx & 7;
        sP[l * 9 + j] = g_U[((long)(l * NN + n)) * 512 + c * 8 + j];
    }
    __syncthreads();

    float acc = convb[c];
#pragma unroll
    for (int k = 0; k < 8; ++k) {
        int l = f - k;
        if (l >= 0 && l < LL) acc += sP[l * 9 + k];
    }
    int b = n >> 7, t = n & 127;
    long oi = (((long)(b * CC + c) * TT + t) << 7) + f;
    out[oi] = acc + g_xn[oi];
}

// ---------------------------------------------------------------------------
// Launch
// ---------------------------------------------------------------------------
extern "C" void kernel_launch(void* const* d_in, const int* in_sizes, int n_in,
                              void* d_out, int out_size)
{
    const float* x     = (const float*)d_in[0];
    const float* gamma = (const float*)d_in[1];
    const float* beta  = (const float*)d_in[2];
    const float* W0  = (const float*)d_in[3];
    const float* bf0 = (const float*)d_in[4];
    const float* br0 = (const float*)d_in[5];
    const float* W1  = (const float*)d_in[6];
    const float* bf1 = (const float*)d_in[7];
    const float* br1 = (const float*)d_in[8];
    const float* W2  = (const float*)d_in[9];
    const float* bf2 = (const float*)d_in[10];
    const float* br2 = (const float*)d_in[11];
    const float* W3  = (const float*)d_in[12];
    const float* bf3 = (const float*)d_in[13];
    const float* br3 = (const float*)d_in[14];
    const float* convW = (const float*)d_in[15];
    const float* convb = (const float*)d_in[16];
    float* out = (float*)d_out;

    cudaFuncSetAttribute(mma_gemm, cudaFuncAttributeMaxDynamicSharedMemorySize,
                         SMEM_DYN);

    wsplit_kernel<<<5632, 256>>>(W0, W1, W2, W3, convW);
    norm_kernel<<<256, 256>>>(x, gamma, beta);
    unfold_kernel<<<123904, 256>>>();

    dim3 gU(4, 484);   // N=1024: 4 N-tiles of 256
    dim3 gP(2, 484);   // N=512:  2 N-tiles of 256

    // Layer 0 (K=512)
    mma_gemm<<<gU, 256, SMEM_DYN>>>(0, 0L, 512, 1024);
    scan_kernel<<<512, 256>>>(bf0, br0);
    // Layers 1-3 (K=256)
    mma_gemm<<<gU, 256, SMEM_DYN>>>(1, 524288L, 256, 1024);
    scan_kernel<<<512, 256>>>(bf1, br1);
    mma_gemm<<<gU, 256, SMEM_DYN>>>(1, 786432L, 256, 1024);
    scan_kernel<<<512, 256>>>(bf2, br2);
    mma_gemm<<<gU, 256, SMEM_DYN>>>(1, 1048576L, 256, 1024);
    scan_kernel<<<512, 256>>>(bf3, br3);

    // ConvTranspose as GEMM: P = h4 @ convW^T  (M x 512, K=256)
    mma_gemm<<<gP, 256, SMEM_DYN>>>(1, 1310720L, 256, 512);

    dim3 gg(CC, NN);
    gather_kernel<<<gg, 128>>>(convb, out);
}